// round 1
// baseline (speedup 1.0000x reference)
#include <cuda_runtime.h>
#include <math.h>

// ---------------- problem dims ----------------
#define BATCH   8
#define SEQ     512
#define NTOK    4096          // BATCH*SEQ
#define DMODEL  1024
#define NHEAD   16
#define DHEAD   64
#define DFF     4096
#define NLAYER  6
#define KVW     2048          // H*(DQ+DV)

// ---------------- scratch (device globals; no allocation allowed) ----------------
__device__ float g_x  [(size_t)NTOK * DMODEL];
__device__ float g_h  [(size_t)NTOK * DMODEL];
__device__ float g_q  [(size_t)NTOK * DMODEL];
__device__ float g_kv [(size_t)NTOK * KVW];
__device__ float g_sc [(size_t)BATCH * NHEAD * SEQ * SEQ];   // 128 MB
__device__ float g_o  [(size_t)NTOK * DMODEL];
__device__ float g_ffn[(size_t)NTOK * DFF];
__device__ float g_pe [(size_t)SEQ * DMODEL];

// ---------------- positional encoding (double precision, matches ref) ----------------
__global__ void pe_kernel(float* __restrict__ pe) {
    int idx = blockIdx.x * 256 + threadIdx.x;
    if (idx >= SEQ * DMODEL) return;
    int s = idx >> 10;
    int d = idx & 1023;
    double e   = (double)(2 * (d >> 1)) / 1024.0;
    double ang = (double)s * exp(-e * log(10000.0));  // s / 10000^e
    pe[idx] = (d & 1) ? (float)cos(ang) : (float)sin(ang);
}

// ---------------- embedding + PE ----------------
__global__ void embed_kernel(const int* __restrict__ tokens,
                             const float* __restrict__ emb,
                             const float* __restrict__ pe,
                             float* __restrict__ x) {
    int idx = blockIdx.x * 256 + threadIdx.x;
    if (idx >= NTOK * DMODEL) return;
    int row = idx >> 10;
    int d   = idx & 1023;
    int s   = row & (SEQ - 1);
    x[idx] = emb[(size_t)tokens[row] * DMODEL + d] * 32.0f + pe[(s << 10) + d];
}

// ---------------- layernorm: one block (256 thr) per row of 1024 ----------------
__global__ void __launch_bounds__(256) ln_kernel(const float* __restrict__ in,
                                                 const float* __restrict__ g,
                                                 const float* __restrict__ b,
                                                 float* __restrict__ out) {
    int row = blockIdx.x;
    const float* xr = in + (size_t)row * DMODEL;
    float v[4];
    float s = 0.f, s2 = 0.f;
#pragma unroll
    for (int i = 0; i < 4; i++) {
        v[i] = xr[threadIdx.x + i * 256];
        s  += v[i];
        s2 += v[i] * v[i];
    }
    __shared__ float rs[8], rs2[8];
#pragma unroll
    for (int off = 16; off; off >>= 1) {
        s  += __shfl_xor_sync(0xffffffffu, s,  off);
        s2 += __shfl_xor_sync(0xffffffffu, s2, off);
    }
    if ((threadIdx.x & 31) == 0) { rs[threadIdx.x >> 5] = s; rs2[threadIdx.x >> 5] = s2; }
    __syncthreads();
    if (threadIdx.x < 32) {
        s  = (threadIdx.x < 8) ? rs [threadIdx.x] : 0.f;
        s2 = (threadIdx.x < 8) ? rs2[threadIdx.x] : 0.f;
#pragma unroll
        for (int off = 4; off; off >>= 1) {
            s  += __shfl_xor_sync(0xffffffffu, s,  off);
            s2 += __shfl_xor_sync(0xffffffffu, s2, off);
        }
        if (threadIdx.x == 0) { rs[0] = s; rs2[0] = s2; }
    }
    __syncthreads();
    float m    = rs[0] * (1.f / DMODEL);
    float var  = rs2[0] * (1.f / DMODEL) - m * m;
    float rstd = rsqrtf(var + 1e-5f);
    float* orow = out + (size_t)row * DMODEL;
#pragma unroll
    for (int i = 0; i < 4; i++) {
        int c = threadIdx.x + i * 256;
        orow[c] = (v[i] - m) * rstd * g[c] + b[c];
    }
}

// ---------------- generic GEMM: C = [res +] A[M,K] @ W[K,N] + bias  (opt relu) ----------------
// 128x128 tile, BK=16, 256 threads, 8x8 per thread. Dims assumed multiples of 128/16.
template <int RELU, int RES>
__global__ void __launch_bounds__(256) gemm_kernel(const float* __restrict__ A,
                                                   const float* __restrict__ W,
                                                   const float* __restrict__ bias,
                                                   const float* __restrict__ R,
                                                   float* __restrict__ C,
                                                   int M, int N, int K) {
    __shared__ float As[16][132];
    __shared__ float Bs[16][132];
    int bm = blockIdx.y << 7;
    int bn = blockIdx.x << 7;
    int tid = threadIdx.x;
    int tx = tid & 15, ty = tid >> 4;
    float acc[8][8] = {};

    for (int k0 = 0; k0 < K; k0 += 16) {
#pragma unroll
        for (int i = 0; i < 2; i++) {
            int idx = tid + i * 256;          // 0..511
            int r   = idx >> 2;               // 0..127  (M row)
            int kq  = (idx & 3) << 2;         // 0,4,8,12 (K)
            float4 va = *(const float4*)(A + (size_t)(bm + r) * K + k0 + kq);
            As[kq + 0][r] = va.x; As[kq + 1][r] = va.y;
            As[kq + 2][r] = va.z; As[kq + 3][r] = va.w;
        }
#pragma unroll
        for (int i = 0; i < 2; i++) {
            int idx = tid + i * 256;
            int r   = idx >> 5;               // k 0..15
            int c   = (idx & 31) << 2;        // n 0..124
            *(float4*)&Bs[r][c] = *(const float4*)(W + (size_t)(k0 + r) * N + bn + c);
        }
        __syncthreads();
#pragma unroll
        for (int k = 0; k < 16; k++) {
            float ra[8], rb[8];
#pragma unroll
            for (int i = 0; i < 8; i++) ra[i] = As[k][ty * 8 + i];
#pragma unroll
            for (int j = 0; j < 8; j++) rb[j] = Bs[k][tx * 8 + j];
#pragma unroll
            for (int i = 0; i < 8; i++)
#pragma unroll
                for (int j = 0; j < 8; j++)
                    acc[i][j] = fmaf(ra[i], rb[j], acc[i][j]);
        }
        __syncthreads();
    }

#pragma unroll
    for (int i = 0; i < 8; i++) {
        int row = bm + ty * 8 + i;
#pragma unroll
        for (int j = 0; j < 8; j += 4) {
            int col = bn + tx * 8 + j;
            float4 outv;
            float* po = (float*)&outv;
#pragma unroll
            for (int t = 0; t < 4; t++) {
                float vv = acc[i][j + t] + bias[col + t];
                if (RES)  vv += R[(size_t)row * N + col + t];
                if (RELU) vv = fmaxf(vv, 0.f);
                po[t] = vv;
            }
            *(float4*)(C + (size_t)row * N + col) = outv;
        }
    }
}

// ---------------- scores: sc[bh, qi, ki] = (q . k) * 1/8 ; batched over B*H ----------------
__global__ void __launch_bounds__(256) scores_kernel(const float* __restrict__ q,
                                                     const float* __restrict__ kv,
                                                     float* __restrict__ sc) {
    int bh = blockIdx.z;
    int b = bh >> 4, h = bh & 15;
    int qi0 = blockIdx.y << 6, ki0 = blockIdx.x << 6;
    __shared__ float Qs[16][68], Ks[16][68];
    int tid = threadIdx.x;
    int tx = tid & 15, ty = tid >> 4;
    float acc[4][4] = {};
    const float* qbase = q  + ((size_t)(b * SEQ) + qi0) * DMODEL + h * DHEAD;
    const float* kbase = kv + ((size_t)(b * SEQ) + ki0) * KVW    + h * DHEAD;
    int lr = tid >> 2, lc = (tid & 3) << 2;
    for (int d0 = 0; d0 < DHEAD; d0 += 16) {
        float4 qv = *(const float4*)(qbase + (size_t)lr * DMODEL + d0 + lc);
        Qs[lc + 0][lr] = qv.x; Qs[lc + 1][lr] = qv.y;
        Qs[lc + 2][lr] = qv.z; Qs[lc + 3][lr] = qv.w;
        float4 kk = *(const float4*)(kbase + (size_t)lr * KVW + d0 + lc);
        Ks[lc + 0][lr] = kk.x; Ks[lc + 1][lr] = kk.y;
        Ks[lc + 2][lr] = kk.z; Ks[lc + 3][lr] = kk.w;
        __syncthreads();
#pragma unroll
        for (int k = 0; k < 16; k++) {
            float ra[4], rb[4];
#pragma unroll
            for (int i = 0; i < 4; i++) ra[i] = Qs[k][ty * 4 + i];
#pragma unroll
            for (int j = 0; j < 4; j++) rb[j] = Ks[k][tx * 4 + j];
#pragma unroll
            for (int i = 0; i < 4; i++)
#pragma unroll
                for (int j = 0; j < 4; j++)
                    acc[i][j] = fmaf(ra[i], rb[j], acc[i][j]);
        }
        __syncthreads();
    }
#pragma unroll
    for (int i = 0; i < 4; i++) {
        float* srow = sc + ((size_t)bh * SEQ + qi0 + ty * 4 + i) * SEQ + ki0 + tx * 4;
        *(float4*)srow = make_float4(acc[i][0] * 0.125f, acc[i][1] * 0.125f,
                                     acc[i][2] * 0.125f, acc[i][3] * 0.125f);
    }
}

// ---------------- masked softmax, one warp per row of 512 ----------------
__global__ void __launch_bounds__(256) softmax_kernel(float* __restrict__ sc,
                                                      const int* __restrict__ lengths) {
    int gw   = (blockIdx.x * blockDim.x + threadIdx.x) >> 5;  // global row
    int lane = threadIdx.x & 31;
    if (gw >= BATCH * NHEAD * SEQ) return;
    int b   = gw >> 13;                 // / (NHEAD*SEQ)
    int len = lengths[b];
    float* row = sc + (size_t)gw * SEQ;
    float v[16];
    float mx = -1e30f;
#pragma unroll
    for (int i = 0; i < 16; i++) {
        int c = lane + i * 32;
        v[i] = (c < len) ? row[c] : -1e30f;
        mx = fmaxf(mx, v[i]);
    }
#pragma unroll
    for (int off = 16; off; off >>= 1) mx = fmaxf(mx, __shfl_xor_sync(0xffffffffu, mx, off));
    float s = 0.f;
#pragma unroll
    for (int i = 0; i < 16; i++) {
        int c = lane + i * 32;
        v[i] = (c < len) ? __expf(v[i] - mx) : 0.f;
        s += v[i];
    }
#pragma unroll
    for (int off = 16; off; off >>= 1) s += __shfl_xor_sync(0xffffffffu, s, off);
    float inv = 1.f / s;
#pragma unroll
    for (int i = 0; i < 16; i++) row[lane + i * 32] = v[i] * inv;
}

// ---------------- AV: o[b,qi,h,:] = sum_ki P[bh,qi,ki] * V[b,ki,h,:] ----------------
__global__ void __launch_bounds__(256) av_kernel(const float* __restrict__ sc,
                                                 const float* __restrict__ kv,
                                                 float* __restrict__ o) {
    int bh = blockIdx.z;
    int b = bh >> 4, h = bh & 15;
    int qi0 = blockIdx.y << 6;
    __shared__ float Ps[16][68], Vs[16][68];
    int tid = threadIdx.x;
    int tx = tid & 15, ty = tid >> 4;
    float acc[4][4] = {};
    const float* prow  = sc + ((size_t)bh * SEQ + qi0) * SEQ;
    const float* vbase = kv + (size_t)b * SEQ * KVW + NHEAD * DHEAD + h * DHEAD;
    int lr = tid >> 2, lc = (tid & 3) << 2;
    int vr = tid >> 4, vc = (tid & 15) << 2;
    for (int k0 = 0; k0 < SEQ; k0 += 16) {
        float4 pv = *(const float4*)(prow + (size_t)lr * SEQ + k0 + lc);
        Ps[lc + 0][lr] = pv.x; Ps[lc + 1][lr] = pv.y;
        Ps[lc + 2][lr] = pv.z; Ps[lc + 3][lr] = pv.w;
        *(float4*)&Vs[vr][vc] = *(const float4*)(vbase + (size_t)(k0 + vr) * KVW + vc);
        __syncthreads();
#pragma unroll
        for (int k = 0; k < 16; k++) {
            float ra[4], rb[4];
#pragma unroll
            for (int i = 0; i < 4; i++) ra[i] = Ps[k][ty * 4 + i];
#pragma unroll
            for (int j = 0; j < 4; j++) rb[j] = Vs[k][tx * 4 + j];
#pragma unroll
            for (int i = 0; i < 4; i++)
#pragma unroll
                for (int j = 0; j < 4; j++)
                    acc[i][j] = fmaf(ra[i], rb[j], acc[i][j]);
        }
        __syncthreads();
    }
#pragma unroll
    for (int i = 0; i < 4; i++) {
        float* orow = o + ((size_t)(b * SEQ) + qi0 + ty * 4 + i) * DMODEL + h * DHEAD + tx * 4;
        *(float4*)orow = make_float4(acc[i][0], acc[i][1], acc[i][2], acc[i][3]);
    }
}

// ---------------- host orchestration ----------------
extern "C" void kernel_launch(void* const* d_in, const int* in_sizes, int n_in,
                              void* d_out, int out_size) {
    const int*   tokens = (const int*)  d_in[0];
    const int*   lengths= (const int*)  d_in[1];
    const float* emb    = (const float*)d_in[2];
    const float* Wq     = (const float*)d_in[3];
    const float* bq     = (const float*)d_in[4];
    const float* Wkv    = (const float*)d_in[5];
    const float* bkv    = (const float*)d_in[6];
    const float* Wo     = (const float*)d_in[7];
    const float* bo     = (const float*)d_in[8];
    const float* lag    = (const float*)d_in[9];
    const float* lab    = (const float*)d_in[10];
    const float* W1     = (const float*)d_in[11];
    const float* b1     = (const float*)d_in[12];
    const float* W2     = (const float*)d_in[13];
    const float* b2     = (const float*)d_in[14];
    const float* lfg    = (const float*)d_in[15];   // ln_ffn_g
    const float* lfb    = (const float*)d_in[16];   // ln_ffn_b
    const float* lng    = (const float*)d_in[17];   // ln_f_g
    const float* lnb    = (const float*)d_in[18];   // ln_f_b

    float *x, *h, *q, *kv, *sc, *o, *ffn, *pe;
    cudaGetSymbolAddress((void**)&x,   g_x);
    cudaGetSymbolAddress((void**)&h,   g_h);
    cudaGetSymbolAddress((void**)&q,   g_q);
    cudaGetSymbolAddress((void**)&kv,  g_kv);
    cudaGetSymbolAddress((void**)&sc,  g_sc);
    cudaGetSymbolAddress((void**)&o,   g_o);
    cudaGetSymbolAddress((void**)&ffn, g_ffn);
    cudaGetSymbolAddress((void**)&pe,  g_pe);

    pe_kernel   <<<(SEQ * DMODEL) / 256, 256>>>(pe);
    embed_kernel<<<(NTOK * DMODEL) / 256, 256>>>(tokens, emb, pe, x);

    for (int l = 0; l < NLAYER; l++) {
        const float* wq  = Wq  + (size_t)l * DMODEL * DMODEL;
        const float* wkv = Wkv + (size_t)l * DMODEL * KVW;
        const float* wo  = Wo  + (size_t)l * DMODEL * DMODEL;
        const float* w1  = W1  + (size_t)l * DMODEL * DFF;
        const float* w2  = W2  + (size_t)l * DFF * DMODEL;

        // attention sublayer
        ln_kernel<<<NTOK, 256>>>(x, lag + l * DMODEL, lab + l * DMODEL, h);
        gemm_kernel<0,0><<<dim3(DMODEL/128, NTOK/128), 256>>>(h, wq,  bq  + l*DMODEL, nullptr, q,  NTOK, DMODEL, DMODEL);
        gemm_kernel<0,0><<<dim3(KVW/128,    NTOK/128), 256>>>(h, wkv, bkv + l*KVW,    nullptr, kv, NTOK, KVW,    DMODEL);
        scores_kernel <<<dim3(SEQ/64, SEQ/64, BATCH*NHEAD), 256>>>(q, kv, sc);
        softmax_kernel<<<(BATCH*NHEAD*SEQ*32)/256, 256>>>(sc, lengths);
        av_kernel     <<<dim3(1, SEQ/64, BATCH*NHEAD), 256>>>(sc, kv, o);
        gemm_kernel<0,1><<<dim3(DMODEL/128, NTOK/128), 256>>>(o, wo, bo + l*DMODEL, x, x, NTOK, DMODEL, DMODEL);

        // FFN sublayer
        ln_kernel<<<NTOK, 256>>>(x, lfg + l * DMODEL, lfb + l * DMODEL, h);
        gemm_kernel<1,0><<<dim3(DFF/128,    NTOK/128), 256>>>(h,   w1, b1 + l*DFF,    nullptr, ffn, NTOK, DFF,    DMODEL);
        gemm_kernel<0,1><<<dim3(DMODEL/128, NTOK/128), 256>>>(ffn, w2, b2 + l*DMODEL, x,       x,   NTOK, DMODEL, DFF);
    }

    ln_kernel<<<NTOK, 256>>>(x, lng, lnb, (float*)d_out);
}

// round 3
// speedup vs baseline: 1.8697x; 1.8697x over previous
#include <cuda_runtime.h>
#include <cuda_bf16.h>
#include <math.h>
#include <stdint.h>

// ---------------- problem dims ----------------
#define BATCH   8
#define SEQ     512
#define NTOK    4096
#define DMODEL  1024
#define NHEAD   16
#define DHEAD   64
#define DFF     4096
#define NLAYER  6
#define KVW     2048

typedef __nv_bfloat16 bf16;

// ---------------- scratch ----------------
__device__ float g_x  [(size_t)NTOK * DMODEL];
__device__ float g_q  [(size_t)NTOK * DMODEL];
__device__ float g_kv [(size_t)NTOK * KVW];
__device__ float g_sc [(size_t)BATCH * NHEAD * SEQ * SEQ];
__device__ float g_pe [(size_t)SEQ * DMODEL];

__device__ bf16 g_hh[(size_t)NTOK * DMODEL];
__device__ bf16 g_hl[(size_t)NTOK * DMODEL];
__device__ bf16 g_oh[(size_t)NTOK * DMODEL];
__device__ bf16 g_ol[(size_t)NTOK * DMODEL];
__device__ bf16 g_fh[(size_t)NTOK * DFF];
__device__ bf16 g_fl[(size_t)NTOK * DFF];

// transposed+split weights: [N,K] bf16 hi/lo
__device__ bf16 g_wqT_h[(size_t)NLAYER * DMODEL * DMODEL];
__device__ bf16 g_wqT_l[(size_t)NLAYER * DMODEL * DMODEL];
__device__ bf16 g_wkvT_h[(size_t)NLAYER * DMODEL * KVW];
__device__ bf16 g_wkvT_l[(size_t)NLAYER * DMODEL * KVW];
__device__ bf16 g_woT_h[(size_t)NLAYER * DMODEL * DMODEL];
__device__ bf16 g_woT_l[(size_t)NLAYER * DMODEL * DMODEL];
__device__ bf16 g_w1T_h[(size_t)NLAYER * DMODEL * DFF];
__device__ bf16 g_w1T_l[(size_t)NLAYER * DMODEL * DFF];
__device__ bf16 g_w2T_h[(size_t)NLAYER * DFF * DMODEL];
__device__ bf16 g_w2T_l[(size_t)NLAYER * DFF * DMODEL];

// ---------------- helpers ----------------
__device__ __forceinline__ uint32_t smem_u32(const void* p) {
    uint32_t a;
    asm("{ .reg .u64 t; cvta.to.shared.u64 t, %1; cvt.u32.u64 %0, t; }" : "=r"(a) : "l"(p));
    return a;
}
#define CP_ASYNC16(dst, src) \
    asm volatile("cp.async.cg.shared.global [%0], [%1], 16;" :: "r"(dst), "l"(src) : "memory")
#define CP_COMMIT() asm volatile("cp.async.commit_group;" ::: "memory")
#define CP_WAIT2()  asm volatile("cp.async.wait_group 2;" ::: "memory")
#define CP_WAIT1()  asm volatile("cp.async.wait_group 1;" ::: "memory")
#define CP_WAIT0()  asm volatile("cp.async.wait_group 0;" ::: "memory")

__device__ __forceinline__ void ldsm4(uint32_t* r, uint32_t addr) {
    asm volatile("ldmatrix.sync.aligned.m8n8.x4.shared.b16 {%0,%1,%2,%3}, [%4];"
        : "=r"(r[0]), "=r"(r[1]), "=r"(r[2]), "=r"(r[3]) : "r"(addr));
}
__device__ __forceinline__ void mma16816(float* d, const uint32_t* a, const uint32_t* b) {
    asm volatile("mma.sync.aligned.m16n8k16.row.col.f32.bf16.bf16.f32 "
        "{%0,%1,%2,%3}, {%4,%5,%6,%7}, {%8,%9}, {%0,%1,%2,%3};"
        : "+f"(d[0]), "+f"(d[1]), "+f"(d[2]), "+f"(d[3])
        : "r"(a[0]), "r"(a[1]), "r"(a[2]), "r"(a[3]), "r"(b[0]), "r"(b[1]));
}

// ---------------- mma.sync GEMM: C[M,N] = A @ Bt^T, bf16x3 (AhBh + AhBl + AlBh) ----------------
// CTA 128x128, 8 warps (2x4), warp tile 64x32, BK=32, 3-stage cp.async pipeline.
// smem rows padded to 80B (conflict-free ldmatrix). MODE 0: fp32+bias; 1: +residual; 2: relu->bf16 hi/lo
#define ROWB   80
#define OFF_AH 0
#define OFF_AL 10240
#define OFF_BH 20480
#define OFF_BL 30720
#define STAGE  40960
#define NSTAGE 3
#define SMEM_T (NSTAGE * STAGE)

template <int MODE>
__global__ void __launch_bounds__(256) tgemm(const bf16* __restrict__ Ah, const bf16* __restrict__ Al,
                                             const bf16* __restrict__ Bh, const bf16* __restrict__ Bl,
                                             const float* __restrict__ bias,
                                             float* __restrict__ Cf,
                                             bf16* __restrict__ Ch, bf16* __restrict__ Cl,
                                             int N, int K) {
    extern __shared__ char smem[];
    const uint32_t sb = smem_u32(smem);
    const int tid  = threadIdx.x;
    const int wid  = tid >> 5, lane = tid & 31;
    const int wm   = wid >> 2, wn = wid & 3;       // warp grid 2 x 4
    const int bm   = blockIdx.y << 7;
    const int bn   = blockIdx.x << 7;
    const int T    = K >> 5;

    float acc[4][4][4] = {};

    auto load_stage = [&](int sidx, int k0) {
        uint32_t stg = sb + sidx * STAGE;
#pragma unroll
        for (int i = 0; i < 4; i++) {
            int flat = tid + i * 256;           // 0..1023
            int half = flat >> 9;               // 0: hi, 1: lo
            int idx  = flat & 511;
            int r = idx >> 2, c = idx & 3;
            const bf16* src = (half ? Al : Ah) + (size_t)(bm + r) * K + k0 + c * 8;
            CP_ASYNC16(stg + (half ? OFF_AL : OFF_AH) + r * ROWB + c * 16, src);
        }
#pragma unroll
        for (int i = 0; i < 4; i++) {
            int flat = tid + i * 256;
            int half = flat >> 9;
            int idx  = flat & 511;
            int r = idx >> 2, c = idx & 3;
            const bf16* src = (half ? Bl : Bh) + (size_t)(bn + r) * K + k0 + c * 8;
            CP_ASYNC16(stg + (half ? OFF_BL : OFF_BH) + r * ROWB + c * 16, src);
        }
        CP_COMMIT();
    };

    // prologue: stages 0,1
    load_stage(0, 0);
    load_stage(1, 32);

    // per-lane ldmatrix address components
    const int aRow  = lane & 15;                 // m row within 16
    const int aKc   = (lane >> 4) * 16;          // k 0-7 / 8-15 (bytes)
    const int bNloc = ((lane >> 4) << 3) + (lane & 7);  // n within 16
    const int bKc   = ((lane >> 3) & 1) * 16;    // k chunk (bytes)

    for (int it = 0; it < T; it++) {
        if (it + 2 < T) load_stage((it + 2) % NSTAGE, (it + 2) << 5);
        int remain = T - 1 - it;
        if (remain >= 2)      { CP_WAIT2(); }
        else if (remain == 1) { CP_WAIT1(); }
        else                  { CP_WAIT0(); }
        __syncthreads();

        uint32_t stg = sb + (it % NSTAGE) * STAGE;
        uint32_t aH = stg + OFF_AH + (wm * 64 + aRow) * ROWB + aKc;
        uint32_t aL = stg + OFF_AL + (wm * 64 + aRow) * ROWB + aKc;
        uint32_t bH = stg + OFF_BH + (wn * 32 + bNloc) * ROWB + bKc;
        uint32_t bL = stg + OFF_BL + (wn * 32 + bNloc) * ROWB + bKc;

#pragma unroll
        for (int kk = 0; kk < 2; kk++) {
            uint32_t ka = kk * 32;
            uint32_t ah[4][4], al[4][4], bh[4][2], bl[4][2];
#pragma unroll
            for (int mi = 0; mi < 4; mi++) {
                ldsm4(ah[mi], aH + mi * 16 * ROWB + ka);
                ldsm4(al[mi], aL + mi * 16 * ROWB + ka);
            }
#pragma unroll
            for (int ni2 = 0; ni2 < 2; ni2++) {
                uint32_t r[4];
                ldsm4(r, bH + ni2 * 16 * ROWB + ka);
                bh[ni2 * 2][0] = r[0]; bh[ni2 * 2][1] = r[1];
                bh[ni2 * 2 + 1][0] = r[2]; bh[ni2 * 2 + 1][1] = r[3];
                ldsm4(r, bL + ni2 * 16 * ROWB + ka);
                bl[ni2 * 2][0] = r[0]; bl[ni2 * 2][1] = r[1];
                bl[ni2 * 2 + 1][0] = r[2]; bl[ni2 * 2 + 1][1] = r[3];
            }
#pragma unroll
            for (int mi = 0; mi < 4; mi++)
#pragma unroll
                for (int ni = 0; ni < 4; ni++) {
                    mma16816(acc[mi][ni], ah[mi], bh[ni]);
                    mma16816(acc[mi][ni], ah[mi], bl[ni]);
                    mma16816(acc[mi][ni], al[mi], bh[ni]);
                }
        }
        __syncthreads();
    }

    // epilogue: accums in registers
#pragma unroll
    for (int mi = 0; mi < 4; mi++) {
        int row0 = bm + wm * 64 + mi * 16 + (lane >> 2);
#pragma unroll
        for (int ni = 0; ni < 4; ni++) {
            int col = bn + wn * 32 + ni * 8 + (lane & 3) * 2;
            float b0 = bias[col], b1 = bias[col + 1];
#pragma unroll
            for (int half = 0; half < 2; half++) {
                int row = row0 + half * 8;
                float v0 = acc[mi][ni][half * 2]     + b0;
                float v1 = acc[mi][ni][half * 2 + 1] + b1;
                if (MODE == 2) {
                    v0 = fmaxf(v0, 0.f); v1 = fmaxf(v1, 0.f);
                    bf16 h0 = __float2bfloat16(v0), h1 = __float2bfloat16(v1);
                    bf16 l0 = __float2bfloat16(v0 - __bfloat162float(h0));
                    bf16 l1 = __float2bfloat16(v1 - __bfloat162float(h1));
                    __nv_bfloat162 ph; ph.x = h0; ph.y = h1;
                    __nv_bfloat162 pl; pl.x = l0; pl.y = l1;
                    *(uint32_t*)(Ch + (size_t)row * N + col) = *(uint32_t*)&ph;
                    *(uint32_t*)(Cl + (size_t)row * N + col) = *(uint32_t*)&pl;
                } else {
                    float* dst = Cf + (size_t)row * N + col;
                    if (MODE == 1) { v0 += dst[0]; v1 += dst[1]; }
                    float2 o; o.x = v0; o.y = v1;
                    *(float2*)dst = o;
                }
            }
        }
    }
}

// ---------------- weight transpose + bf16 split: W[K,N] -> Th/Tl [N,K] ----------------
__global__ void wsplit(const float* __restrict__ W, bf16* __restrict__ Th, bf16* __restrict__ Tl,
                       int K, int N) {
    __shared__ float t[32][33];
    const size_t lo = (size_t)blockIdx.z * K * N;
    const float* Wl = W + lo;
    bf16* th = Th + lo;
    bf16* tl = Tl + lo;
    int k0 = blockIdx.y << 5, n0 = blockIdx.x << 5;
    int tx = threadIdx.x, ty = threadIdx.y;
#pragma unroll
    for (int i = 0; i < 4; i++)
        t[ty + i * 8][tx] = Wl[(size_t)(k0 + ty + i * 8) * N + n0 + tx];
    __syncthreads();
#pragma unroll
    for (int i = 0; i < 4; i++) {
        float v = t[tx][ty + i * 8];
        bf16 h = __float2bfloat16(v);
        size_t di = (size_t)(n0 + ty + i * 8) * K + k0 + tx;
        th[di] = h;
        tl[di] = __float2bfloat16(v - __bfloat162float(h));
    }
}

// ---------------- positional encoding ----------------
__global__ void pe_kernel(float* __restrict__ pe) {
    int idx = blockIdx.x * 256 + threadIdx.x;
    if (idx >= SEQ * DMODEL) return;
    int s = idx >> 10;
    int d = idx & 1023;
    double e = (double)(2 * (d >> 1)) / 1024.0;
    double ang = (double)s * exp(-e * log(10000.0));
    pe[idx] = (d & 1) ? (float)cos(ang) : (float)sin(ang);
}

// ---------------- embedding + PE ----------------
__global__ void embed_kernel(const int* __restrict__ tokens, const float* __restrict__ emb,
                             const float* __restrict__ pe, float* __restrict__ x) {
    int idx = blockIdx.x * 256 + threadIdx.x;
    if (idx >= NTOK * DMODEL) return;
    int row = idx >> 10;
    int d = idx & 1023;
    int s = row & (SEQ - 1);
    x[idx] = emb[(size_t)tokens[row] * DMODEL + d] * 32.0f + pe[(s << 10) + d];
}

// ---------------- layernorm (SPLIT=1 -> bf16 hi/lo out; 0 -> fp32 out) ----------------
template <int SPLIT>
__global__ void __launch_bounds__(256) ln_kernel(const float* __restrict__ in,
                                                 const float* __restrict__ g,
                                                 const float* __restrict__ b,
                                                 float* __restrict__ outf,
                                                 bf16* __restrict__ oh, bf16* __restrict__ ol) {
    int row = blockIdx.x;
    const float* xr = in + (size_t)row * DMODEL;
    float v[4];
    float s = 0.f, s2 = 0.f;
#pragma unroll
    for (int i = 0; i < 4; i++) {
        v[i] = xr[threadIdx.x + i * 256];
        s += v[i]; s2 += v[i] * v[i];
    }
    __shared__ float rs[8], rs2[8];
#pragma unroll
    for (int off = 16; off; off >>= 1) {
        s  += __shfl_xor_sync(0xffffffffu, s, off);
        s2 += __shfl_xor_sync(0xffffffffu, s2, off);
    }
    if ((threadIdx.x & 31) == 0) { rs[threadIdx.x >> 5] = s; rs2[threadIdx.x >> 5] = s2; }
    __syncthreads();
    if (threadIdx.x < 32) {
        s  = (threadIdx.x < 8) ? rs[threadIdx.x] : 0.f;
        s2 = (threadIdx.x < 8) ? rs2[threadIdx.x] : 0.f;
#pragma unroll
        for (int off = 4; off; off >>= 1) {
            s  += __shfl_xor_sync(0xffffffffu, s, off);
            s2 += __shfl_xor_sync(0xffffffffu, s2, off);
        }
        if (threadIdx.x == 0) { rs[0] = s; rs2[0] = s2; }
    }
    __syncthreads();
    float m = rs[0] * (1.f / DMODEL);
    float var = rs2[0] * (1.f / DMODEL) - m * m;
    float rstd = rsqrtf(var + 1e-5f);
#pragma unroll
    for (int i = 0; i < 4; i++) {
        int c = threadIdx.x + i * 256;
        float val = (v[i] - m) * rstd * g[c] + b[c];
        if (SPLIT) {
            bf16 h = __float2bfloat16(val);
            oh[(size_t)row * DMODEL + c] = h;
            ol[(size_t)row * DMODEL + c] = __float2bfloat16(val - __bfloat162float(h));
        } else {
            outf[(size_t)row * DMODEL + c] = val;
        }
    }
}

// ---------------- scores ----------------
__global__ void __launch_bounds__(256) scores_kernel(const float* __restrict__ q,
                                                     const float* __restrict__ kv,
                                                     float* __restrict__ sc) {
    int bh = blockIdx.z;
    int b = bh >> 4, h = bh & 15;
    int qi0 = blockIdx.y << 6, ki0 = blockIdx.x << 6;
    __shared__ float Qs[16][68], Ks[16][68];
    int tid = threadIdx.x;
    int tx = tid & 15, ty = tid >> 4;
    float acc[4][4] = {};
    const float* qbase = q  + ((size_t)(b * SEQ) + qi0) * DMODEL + h * DHEAD;
    const float* kbase = kv + ((size_t)(b * SEQ) + ki0) * KVW + h * DHEAD;
    int lr = tid >> 2, lc = (tid & 3) << 2;
    for (int d0 = 0; d0 < DHEAD; d0 += 16) {
        float4 qv = *(const float4*)(qbase + (size_t)lr * DMODEL + d0 + lc);
        Qs[lc + 0][lr] = qv.x; Qs[lc + 1][lr] = qv.y; Qs[lc + 2][lr] = qv.z; Qs[lc + 3][lr] = qv.w;
        float4 kk = *(const float4*)(kbase + (size_t)lr * KVW + d0 + lc);
        Ks[lc + 0][lr] = kk.x; Ks[lc + 1][lr] = kk.y; Ks[lc + 2][lr] = kk.z; Ks[lc + 3][lr] = kk.w;
        __syncthreads();
#pragma unroll
        for (int k = 0; k < 16; k++) {
            float ra[4], rb[4];
#pragma unroll
            for (int i = 0; i < 4; i++) ra[i] = Qs[k][ty * 4 + i];
#pragma unroll
            for (int j = 0; j < 4; j++) rb[j] = Ks[k][tx * 4 + j];
#pragma unroll
            for (int i = 0; i < 4; i++)
#pragma unroll
                for (int j = 0; j < 4; j++)
                    acc[i][j] = fmaf(ra[i], rb[j], acc[i][j]);
        }
        __syncthreads();
    }
#pragma unroll
    for (int i = 0; i < 4; i++) {
        float* srow = sc + ((size_t)bh * SEQ + qi0 + ty * 4 + i) * SEQ + ki0 + tx * 4;
        *(float4*)srow = make_float4(acc[i][0] * 0.125f, acc[i][1] * 0.125f,
                                     acc[i][2] * 0.125f, acc[i][3] * 0.125f);
    }
}

// ---------------- masked softmax ----------------
__global__ void __launch_bounds__(256) softmax_kernel(float* __restrict__ sc,
                                                      const int* __restrict__ lengths) {
    int gw = (blockIdx.x * blockDim.x + threadIdx.x) >> 5;
    int lane = threadIdx.x & 31;
    if (gw >= BATCH * NHEAD * SEQ) return;
    int b = gw >> 13;
    int len = lengths[b];
    float* row = sc + (size_t)gw * SEQ;
    float v[16];
    float mx = -1e30f;
#pragma unroll
    for (int i = 0; i < 16; i++) {
        int c = lane + i * 32;
        v[i] = (c < len) ? row[c] : -1e30f;
        mx = fmaxf(mx, v[i]);
    }
#pragma unroll
    for (int off = 16; off; off >>= 1) mx = fmaxf(mx, __shfl_xor_sync(0xffffffffu, mx, off));
    float s = 0.f;
#pragma unroll
    for (int i = 0; i < 16; i++) {
        int c = lane + i * 32;
        v[i] = (c < len) ? __expf(v[i] - mx) : 0.f;
        s += v[i];
    }
#pragma unroll
    for (int off = 16; off; off >>= 1) s += __shfl_xor_sync(0xffffffffu, s, off);
    float inv = 1.f / s;
#pragma unroll
    for (int i = 0; i < 16; i++) row[lane + i * 32] = v[i] * inv;
}

// ---------------- AV -> bf16 hi/lo ----------------
__global__ void __launch_bounds__(256) av_kernel(const float* __restrict__ sc,
                                                 const float* __restrict__ kv,
                                                 bf16* __restrict__ oh, bf16* __restrict__ ol) {
    int bh = blockIdx.z;
    int b = bh >> 4, h = bh & 15;
    int qi0 = blockIdx.y << 6;
    __shared__ float Ps[16][68], Vs[16][68];
    int tid = threadIdx.x;
    int tx = tid & 15, ty = tid >> 4;
    float acc[4][4] = {};
    const float* prow = sc + ((size_t)bh * SEQ + qi0) * SEQ;
    const float* vbase = kv + (size_t)b * SEQ * KVW + NHEAD * DHEAD + h * DHEAD;
    int lr = tid >> 2, lc = (tid & 3) << 2;
    int vr = tid >> 4, vc = (tid & 15) << 2;
    for (int k0 = 0; k0 < SEQ; k0 += 16) {
        float4 pv = *(const float4*)(prow + (size_t)lr * SEQ + k0 + lc);
        Ps[lc + 0][lr] = pv.x; Ps[lc + 1][lr] = pv.y; Ps[lc + 2][lr] = pv.z; Ps[lc + 3][lr] = pv.w;
        *(float4*)&Vs[vr][vc] = *(const float4*)(vbase + (size_t)(k0 + vr) * KVW + vc);
        __syncthreads();
#pragma unroll
        for (int k = 0; k < 16; k++) {
            float ra[4], rb[4];
#pragma unroll
            for (int i = 0; i < 4; i++) ra[i] = Ps[k][ty * 4 + i];
#pragma unroll
            for (int j = 0; j < 4; j++) rb[j] = Vs[k][tx * 4 + j];
#pragma unroll
            for (int i = 0; i < 4; i++)
#pragma unroll
                for (int j = 0; j < 4; j++)
                    acc[i][j] = fmaf(ra[i], rb[j], acc[i][j]);
        }
        __syncthreads();
    }
#pragma unroll
    for (int i = 0; i < 4; i++) {
        size_t base = ((size_t)(b * SEQ) + qi0 + ty * 4 + i) * DMODEL + h * DHEAD + tx * 4;
#pragma unroll
        for (int j = 0; j < 4; j++) {
            float v = acc[i][j];
            bf16 hh = __float2bfloat16(v);
            oh[base + j] = hh;
            ol[base + j] = __float2bfloat16(v - __bfloat162float(hh));
        }
    }
}

// ---------------- host ----------------
extern "C" void kernel_launch(void* const* d_in, const int* in_sizes, int n_in,
                              void* d_out, int out_size) {
    const int*   tokens = (const int*)  d_in[0];
    const int*   lengths= (const int*)  d_in[1];
    const float* emb    = (const float*)d_in[2];
    const float* Wq     = (const float*)d_in[3];
    const float* bq     = (const float*)d_in[4];
    const float* Wkv    = (const float*)d_in[5];
    const float* bkv    = (const float*)d_in[6];
    const float* Wo     = (const float*)d_in[7];
    const float* bo     = (const float*)d_in[8];
    const float* lag    = (const float*)d_in[9];
    const float* lab    = (const float*)d_in[10];
    const float* W1     = (const float*)d_in[11];
    const float* b1     = (const float*)d_in[12];
    const float* W2     = (const float*)d_in[13];
    const float* b2     = (const float*)d_in[14];
    const float* lfg    = (const float*)d_in[15];
    const float* lfb    = (const float*)d_in[16];
    const float* lng    = (const float*)d_in[17];
    const float* lnb    = (const float*)d_in[18];

    float *x, *q, *kv, *sc, *pe;
    bf16 *hh, *hl, *oh, *ol, *fh, *fl;
    bf16 *wqh, *wql, *wkvh, *wkvl, *woh, *wol, *w1h, *w1l, *w2h, *w2l;
    cudaGetSymbolAddress((void**)&x, g_x);
    cudaGetSymbolAddress((void**)&q, g_q);
    cudaGetSymbolAddress((void**)&kv, g_kv);
    cudaGetSymbolAddress((void**)&sc, g_sc);
    cudaGetSymbolAddress((void**)&pe, g_pe);
    cudaGetSymbolAddress((void**)&hh, g_hh);
    cudaGetSymbolAddress((void**)&hl, g_hl);
    cudaGetSymbolAddress((void**)&oh, g_oh);
    cudaGetSymbolAddress((void**)&ol, g_ol);
    cudaGetSymbolAddress((void**)&fh, g_fh);
    cudaGetSymbolAddress((void**)&fl, g_fl);
    cudaGetSymbolAddress((void**)&wqh, g_wqT_h);  cudaGetSymbolAddress((void**)&wql, g_wqT_l);
    cudaGetSymbolAddress((void**)&wkvh, g_wkvT_h); cudaGetSymbolAddress((void**)&wkvl, g_wkvT_l);
    cudaGetSymbolAddress((void**)&woh, g_woT_h);  cudaGetSymbolAddress((void**)&wol, g_woT_l);
    cudaGetSymbolAddress((void**)&w1h, g_w1T_h);  cudaGetSymbolAddress((void**)&w1l, g_w1T_l);
    cudaGetSymbolAddress((void**)&w2h, g_w2T_h);  cudaGetSymbolAddress((void**)&w2l, g_w2T_l);

    cudaFuncSetAttribute(tgemm<0>, cudaFuncAttributeMaxDynamicSharedMemorySize, SMEM_T);
    cudaFuncSetAttribute(tgemm<1>, cudaFuncAttributeMaxDynamicSharedMemorySize, SMEM_T);
    cudaFuncSetAttribute(tgemm<2>, cudaFuncAttributeMaxDynamicSharedMemorySize, SMEM_T);

    dim3 tb(32, 8);
    wsplit<<<dim3(DMODEL / 32, DMODEL / 32, NLAYER), tb>>>(Wq,  wqh,  wql,  DMODEL, DMODEL);
    wsplit<<<dim3(KVW / 32,    DMODEL / 32, NLAYER), tb>>>(Wkv, wkvh, wkvl, DMODEL, KVW);
    wsplit<<<dim3(DMODEL / 32, DMODEL / 32, NLAYER), tb>>>(Wo,  woh,  wol,  DMODEL, DMODEL);
    wsplit<<<dim3(DFF / 32,    DMODEL / 32, NLAYER), tb>>>(W1,  w1h,  w1l,  DMODEL, DFF);
    wsplit<<<dim3(DMODEL / 32, DFF / 32,    NLAYER), tb>>>(W2,  w2h,  w2l,  DFF,    DMODEL);

    pe_kernel<<<(SEQ * DMODEL) / 256, 256>>>(pe);
    embed_kernel<<<(NTOK * DMODEL) / 256, 256>>>(tokens, emb, pe, x);

    for (int l = 0; l < NLAYER; l++) {
        size_t oQ = (size_t)l * DMODEL * DMODEL;
        size_t oKV = (size_t)l * DMODEL * KVW;
        size_t o1 = (size_t)l * DMODEL * DFF;

        // attention sublayer
        ln_kernel<1><<<NTOK, 256>>>(x, lag + l * DMODEL, lab + l * DMODEL, nullptr, hh, hl);
        tgemm<0><<<dim3(DMODEL / 128, NTOK / 128), 256, SMEM_T>>>(
            hh, hl, wqh + oQ, wql + oQ, bq + l * DMODEL, q, nullptr, nullptr, DMODEL, DMODEL);
        tgemm<0><<<dim3(KVW / 128, NTOK / 128), 256, SMEM_T>>>(
            hh, hl, wkvh + oKV, wkvl + oKV, bkv + l * KVW, kv, nullptr, nullptr, KVW, DMODEL);
        scores_kernel<<<dim3(SEQ / 64, SEQ / 64, BATCH * NHEAD), 256>>>(q, kv, sc);
        softmax_kernel<<<(BATCH * NHEAD * SEQ * 32) / 256, 256>>>(sc, lengths);
        av_kernel<<<dim3(1, SEQ / 64, BATCH * NHEAD), 256>>>(sc, kv, oh, ol);
        tgemm<1><<<dim3(DMODEL / 128, NTOK / 128), 256, SMEM_T>>>(
            oh, ol, woh + oQ, wol + oQ, bo + l * DMODEL, x, nullptr, nullptr, DMODEL, DMODEL);

        // FFN sublayer
        ln_kernel<1><<<NTOK, 256>>>(x, lfg + l * DMODEL, lfb + l * DMODEL, nullptr, hh, hl);
        tgemm<2><<<dim3(DFF / 128, NTOK / 128), 256, SMEM_T>>>(
            hh, hl, w1h + o1, w1l + o1, b1 + l * DFF, nullptr, fh, fl, DFF, DMODEL);
        tgemm<1><<<dim3(DMODEL / 128, NTOK / 128), 256, SMEM_T>>>(
            fh, fl, w2h + o1, w2l + o1, b2 + l * DMODEL, x, nullptr, nullptr, DMODEL, DFF);
    }

    ln_kernel<0><<<NTOK, 256>>>(x, lng, lnb, (float*)d_out, nullptr, nullptr);
}

// round 4
// speedup vs baseline: 1.9735x; 1.0555x over previous
#include <cuda_runtime.h>
#include <cuda_bf16.h>
#include <math.h>
#include <stdint.h>

// ---------------- problem dims ----------------
#define BATCH   8
#define SEQ     512
#define NTOK    4096
#define DMODEL  1024
#define NHEAD   16
#define DHEAD   64
#define DFF     4096
#define NLAYER  6
#define KVW     2048

typedef __nv_bfloat16 bf16;

// ---------------- scratch ----------------
__device__ float g_x  [(size_t)NTOK * DMODEL];
__device__ float g_q  [(size_t)NTOK * DMODEL];
__device__ float g_kv [(size_t)NTOK * KVW];
__device__ float g_sc [(size_t)BATCH * NHEAD * SEQ * SEQ];
__device__ float g_pe [(size_t)SEQ * DMODEL];

__device__ bf16 g_hh[(size_t)NTOK * DMODEL];
__device__ bf16 g_hl[(size_t)NTOK * DMODEL];
__device__ bf16 g_oh[(size_t)NTOK * DMODEL];
__device__ bf16 g_ol[(size_t)NTOK * DMODEL];
__device__ bf16 g_fh[(size_t)NTOK * DFF];
__device__ bf16 g_fl[(size_t)NTOK * DFF];

// transposed+split weights: [N,K] bf16 hi/lo
__device__ bf16 g_wqT_h[(size_t)NLAYER * DMODEL * DMODEL];
__device__ bf16 g_wqT_l[(size_t)NLAYER * DMODEL * DMODEL];
__device__ bf16 g_wkvT_h[(size_t)NLAYER * DMODEL * KVW];
__device__ bf16 g_wkvT_l[(size_t)NLAYER * DMODEL * KVW];
__device__ bf16 g_woT_h[(size_t)NLAYER * DMODEL * DMODEL];
__device__ bf16 g_woT_l[(size_t)NLAYER * DMODEL * DMODEL];
__device__ bf16 g_w1T_h[(size_t)NLAYER * DMODEL * DFF];
__device__ bf16 g_w1T_l[(size_t)NLAYER * DMODEL * DFF];
__device__ bf16 g_w2T_h[(size_t)NLAYER * DFF * DMODEL];
__device__ bf16 g_w2T_l[(size_t)NLAYER * DFF * DMODEL];

// ---------------- helpers ----------------
__device__ __forceinline__ uint32_t smem_u32(const void* p) {
    uint32_t a;
    asm("{ .reg .u64 t; cvta.to.shared.u64 t, %1; cvt.u32.u64 %0, t; }" : "=r"(a) : "l"(p));
    return a;
}
#define CP_ASYNC16(dst, src) \
    asm volatile("cp.async.cg.shared.global [%0], [%1], 16;" :: "r"(dst), "l"(src) : "memory")
#define CP_COMMIT() asm volatile("cp.async.commit_group;" ::: "memory")
#define CP_WAIT2()  asm volatile("cp.async.wait_group 2;" ::: "memory")
#define CP_WAIT1()  asm volatile("cp.async.wait_group 1;" ::: "memory")
#define CP_WAIT0()  asm volatile("cp.async.wait_group 0;" ::: "memory")

__device__ __forceinline__ void ldsm4(uint32_t* r, uint32_t addr) {
    asm volatile("ldmatrix.sync.aligned.m8n8.x4.shared.b16 {%0,%1,%2,%3}, [%4];"
        : "=r"(r[0]), "=r"(r[1]), "=r"(r[2]), "=r"(r[3]) : "r"(addr));
}
__device__ __forceinline__ void mma16816(float* d, const uint32_t* a, const uint32_t* b) {
    asm volatile("mma.sync.aligned.m16n8k16.row.col.f32.bf16.bf16.f32 "
        "{%0,%1,%2,%3}, {%4,%5,%6,%7}, {%8,%9}, {%0,%1,%2,%3};"
        : "+f"(d[0]), "+f"(d[1]), "+f"(d[2]), "+f"(d[3])
        : "r"(a[0]), "r"(a[1]), "r"(a[2]), "r"(a[3]), "r"(b[0]), "r"(b[1]));
}

// ---------------- mma.sync GEMM: C[M,N] = A @ Bt^T, bf16x3 (AhBh + AhBl + AlBh) ----------------
// CTA 128x256, 8 warps (2x4), warp tile 64x64, BK=32, 3-stage cp.async pipeline.
// smem rows padded to 80B. MODE 0: fp32+bias; 1: +residual; 2: relu->bf16 hi/lo
#define ROWB   80
#define OFF_AH 0
#define OFF_AL 10240
#define OFF_BH 20480
#define OFF_BL 40960
#define STAGE  61440
#define NSTAGE 3
#define SMEM_T (NSTAGE * STAGE)

template <int MODE>
__global__ void __launch_bounds__(256) tgemm(const bf16* __restrict__ Ah, const bf16* __restrict__ Al,
                                             const bf16* __restrict__ Bh, const bf16* __restrict__ Bl,
                                             const float* __restrict__ bias,
                                             float* __restrict__ Cf,
                                             bf16* __restrict__ Ch, bf16* __restrict__ Cl,
                                             int N, int K) {
    extern __shared__ char smem[];
    const uint32_t sb = smem_u32(smem);
    const int tid  = threadIdx.x;
    const int wid  = tid >> 5, lane = tid & 31;
    const int wm   = wid >> 2, wn = wid & 3;       // warp grid 2 x 4, warp tile 64x64
    const int bm   = blockIdx.y << 7;
    const int bn   = blockIdx.x << 8;
    const int T    = K >> 5;

    float acc[4][8][4] = {};

    auto load_stage = [&](int sidx, int k0) {
        uint32_t stg = sb + sidx * STAGE;
#pragma unroll
        for (int i = 0; i < 4; i++) {
            int flat = tid + i * 256;           // 0..1023  A hi/lo
            int half = flat >> 9;
            int idx  = flat & 511;
            int r = idx >> 2, c = idx & 3;
            const bf16* src = (half ? Al : Ah) + (size_t)(bm + r) * K + k0 + c * 8;
            CP_ASYNC16(stg + (half ? OFF_AL : OFF_AH) + r * ROWB + c * 16, src);
        }
#pragma unroll
        for (int i = 0; i < 8; i++) {
            int flat = tid + i * 256;           // 0..2047  B hi/lo (256 rows)
            int half = flat >> 10;
            int idx  = flat & 1023;
            int r = idx >> 2, c = idx & 3;
            const bf16* src = (half ? Bl : Bh) + (size_t)(bn + r) * K + k0 + c * 8;
            CP_ASYNC16(stg + (half ? OFF_BL : OFF_BH) + r * ROWB + c * 16, src);
        }
        CP_COMMIT();
    };

    // prologue: stages 0,1
    load_stage(0, 0);
    load_stage(1, 32);

    // per-lane ldmatrix address components
    const int aRow  = lane & 15;                        // m row within 16
    const int aKc   = (lane >> 4) * 16;                 // k byte 0/16
    const int bNloc = ((lane >> 4) << 3) + (lane & 7);  // n within 16
    const int bKc   = ((lane >> 3) & 1) * 16;           // k byte chunk

    for (int it = 0; it < T; it++) {
        if (it + 2 < T) load_stage((it + 2) % NSTAGE, (it + 2) << 5);
        int remain = T - 1 - it;
        if (remain >= 2)      { CP_WAIT2(); }
        else if (remain == 1) { CP_WAIT1(); }
        else                  { CP_WAIT0(); }
        __syncthreads();

        uint32_t stg = sb + (it % NSTAGE) * STAGE;
        uint32_t aH = stg + OFF_AH + (wm * 64 + aRow) * ROWB + aKc;
        uint32_t aL = stg + OFF_AL + (wm * 64 + aRow) * ROWB + aKc;
        uint32_t bH = stg + OFF_BH + (wn * 64 + bNloc) * ROWB + bKc;
        uint32_t bL = stg + OFF_BL + (wn * 64 + bNloc) * ROWB + bKc;

#pragma unroll
        for (int kk = 0; kk < 2; kk++) {
            uint32_t ka = kk * 32;
            uint32_t ah[4][4], al[4][4], bh[8][2], bl[8][2];
#pragma unroll
            for (int mi = 0; mi < 4; mi++) {
                ldsm4(ah[mi], aH + mi * 16 * ROWB + ka);
                ldsm4(al[mi], aL + mi * 16 * ROWB + ka);
            }
#pragma unroll
            for (int ni2 = 0; ni2 < 4; ni2++) {
                uint32_t r[4];
                ldsm4(r, bH + ni2 * 16 * ROWB + ka);
                bh[ni2 * 2][0] = r[0]; bh[ni2 * 2][1] = r[1];
                bh[ni2 * 2 + 1][0] = r[2]; bh[ni2 * 2 + 1][1] = r[3];
                ldsm4(r, bL + ni2 * 16 * ROWB + ka);
                bl[ni2 * 2][0] = r[0]; bl[ni2 * 2][1] = r[1];
                bl[ni2 * 2 + 1][0] = r[2]; bl[ni2 * 2 + 1][1] = r[3];
            }
#pragma unroll
            for (int mi = 0; mi < 4; mi++)
#pragma unroll
                for (int ni = 0; ni < 8; ni++) {
                    mma16816(acc[mi][ni], ah[mi], bh[ni]);
                    mma16816(acc[mi][ni], ah[mi], bl[ni]);
                    mma16816(acc[mi][ni], al[mi], bh[ni]);
                }
        }
        __syncthreads();
    }

    // epilogue
#pragma unroll
    for (int mi = 0; mi < 4; mi++) {
        int row0 = bm + wm * 64 + mi * 16 + (lane >> 2);
#pragma unroll
        for (int ni = 0; ni < 8; ni++) {
            int col = bn + wn * 64 + ni * 8 + (lane & 3) * 2;
            float b0 = bias[col], b1 = bias[col + 1];
#pragma unroll
            for (int half = 0; half < 2; half++) {
                int row = row0 + half * 8;
                float v0 = acc[mi][ni][half * 2]     + b0;
                float v1 = acc[mi][ni][half * 2 + 1] + b1;
                if (MODE == 2) {
                    v0 = fmaxf(v0, 0.f); v1 = fmaxf(v1, 0.f);
                    bf16 h0 = __float2bfloat16(v0), h1 = __float2bfloat16(v1);
                    bf16 l0 = __float2bfloat16(v0 - __bfloat162float(h0));
                    bf16 l1 = __float2bfloat16(v1 - __bfloat162float(h1));
                    __nv_bfloat162 ph; ph.x = h0; ph.y = h1;
                    __nv_bfloat162 pl; pl.x = l0; pl.y = l1;
                    *(uint32_t*)(Ch + (size_t)row * N + col) = *(uint32_t*)&ph;
                    *(uint32_t*)(Cl + (size_t)row * N + col) = *(uint32_t*)&pl;
                } else {
                    float* dst = Cf + (size_t)row * N + col;
                    float v0r = v0, v1r = v1;
                    if (MODE == 1) { v0r += dst[0]; v1r += dst[1]; }
                    float2 o; o.x = v0r; o.y = v1r;
                    *(float2*)dst = o;
                }
            }
        }
    }
}

// ---------------- weight transpose + bf16 split: W[K,N] -> Th/Tl [N,K] ----------------
__global__ void wsplit(const float* __restrict__ W, bf16* __restrict__ Th, bf16* __restrict__ Tl,
                       int K, int N) {
    __shared__ float t[32][33];
    const size_t lo = (size_t)blockIdx.z * K * N;
    const float* Wl = W + lo;
    bf16* th = Th + lo;
    bf16* tl = Tl + lo;
    int k0 = blockIdx.y << 5, n0 = blockIdx.x << 5;
    int tx = threadIdx.x, ty = threadIdx.y;
#pragma unroll
    for (int i = 0; i < 4; i++)
        t[ty + i * 8][tx] = Wl[(size_t)(k0 + ty + i * 8) * N + n0 + tx];
    __syncthreads();
#pragma unroll
    for (int i = 0; i < 4; i++) {
        float v = t[tx][ty + i * 8];
        bf16 h = __float2bfloat16(v);
        size_t di = (size_t)(n0 + ty + i * 8) * K + k0 + tx;
        th[di] = h;
        tl[di] = __float2bfloat16(v - __bfloat162float(h));
    }
}

// ---------------- positional encoding ----------------
__global__ void pe_kernel(float* __restrict__ pe) {
    int idx = blockIdx.x * 256 + threadIdx.x;
    if (idx >= SEQ * DMODEL) return;
    int s = idx >> 10;
    int d = idx & 1023;
    double e = (double)(2 * (d >> 1)) / 1024.0;
    double ang = (double)s * exp(-e * log(10000.0));
    pe[idx] = (d & 1) ? (float)cos(ang) : (float)sin(ang);
}

// ---------------- embedding + PE ----------------
__global__ void embed_kernel(const int* __restrict__ tokens, const float* __restrict__ emb,
                             const float* __restrict__ pe, float* __restrict__ x) {
    int idx = blockIdx.x * 256 + threadIdx.x;
    if (idx >= NTOK * DMODEL) return;
    int row = idx >> 10;
    int d = idx & 1023;
    int s = row & (SEQ - 1);
    x[idx] = emb[(size_t)tokens[row] * DMODEL + d] * 32.0f + pe[(s << 10) + d];
}

// ---------------- layernorm (SPLIT=1 -> bf16 hi/lo out; 0 -> fp32 out) ----------------
template <int SPLIT>
__global__ void __launch_bounds__(256) ln_kernel(const float* __restrict__ in,
                                                 const float* __restrict__ g,
                                                 const float* __restrict__ b,
                                                 float* __restrict__ outf,
                                                 bf16* __restrict__ oh, bf16* __restrict__ ol) {
    int row = blockIdx.x;
    const float* xr = in + (size_t)row * DMODEL;
    float v[4];
    float s = 0.f, s2 = 0.f;
#pragma unroll
    for (int i = 0; i < 4; i++) {
        v[i] = xr[threadIdx.x + i * 256];
        s += v[i]; s2 += v[i] * v[i];
    }
    __shared__ float rs[8], rs2[8];
#pragma unroll
    for (int off = 16; off; off >>= 1) {
        s  += __shfl_xor_sync(0xffffffffu, s, off);
        s2 += __shfl_xor_sync(0xffffffffu, s2, off);
    }
    if ((threadIdx.x & 31) == 0) { rs[threadIdx.x >> 5] = s; rs2[threadIdx.x >> 5] = s2; }
    __syncthreads();
    if (threadIdx.x < 32) {
        s  = (threadIdx.x < 8) ? rs[threadIdx.x] : 0.f;
        s2 = (threadIdx.x < 8) ? rs2[threadIdx.x] : 0.f;
#pragma unroll
        for (int off = 4; off; off >>= 1) {
            s  += __shfl_xor_sync(0xffffffffu, s, off);
            s2 += __shfl_xor_sync(0xffffffffu, s2, off);
        }
        if (threadIdx.x == 0) { rs[0] = s; rs2[0] = s2; }
    }
    __syncthreads();
    float m = rs[0] * (1.f / DMODEL);
    float var = rs2[0] * (1.f / DMODEL) - m * m;
    float rstd = rsqrtf(var + 1e-5f);
#pragma unroll
    for (int i = 0; i < 4; i++) {
        int c = threadIdx.x + i * 256;
        float val = (v[i] - m) * rstd * g[c] + b[c];
        if (SPLIT) {
            bf16 h = __float2bfloat16(val);
            oh[(size_t)row * DMODEL + c] = h;
            ol[(size_t)row * DMODEL + c] = __float2bfloat16(val - __bfloat162float(h));
        } else {
            outf[(size_t)row * DMODEL + c] = val;
        }
    }
}

// ---------------- scores ----------------
__global__ void __launch_bounds__(256) scores_kernel(const float* __restrict__ q,
                                                     const float* __restrict__ kv,
                                                     float* __restrict__ sc) {
    int bh = blockIdx.z;
    int b = bh >> 4, h = bh & 15;
    int qi0 = blockIdx.y << 6, ki0 = blockIdx.x << 6;
    __shared__ float Qs[16][68], Ks[16][68];
    int tid = threadIdx.x;
    int tx = tid & 15, ty = tid >> 4;
    float acc[4][4] = {};
    const float* qbase = q  + ((size_t)(b * SEQ) + qi0) * DMODEL + h * DHEAD;
    const float* kbase = kv + ((size_t)(b * SEQ) + ki0) * KVW + h * DHEAD;
    int lr = tid >> 2, lc = (tid & 3) << 2;
    for (int d0 = 0; d0 < DHEAD; d0 += 16) {
        float4 qv = *(const float4*)(qbase + (size_t)lr * DMODEL + d0 + lc);
        Qs[lc + 0][lr] = qv.x; Qs[lc + 1][lr] = qv.y; Qs[lc + 2][lr] = qv.z; Qs[lc + 3][lr] = qv.w;
        float4 kk = *(const float4*)(kbase + (size_t)lr * KVW + d0 + lc);
        Ks[lc + 0][lr] = kk.x; Ks[lc + 1][lr] = kk.y; Ks[lc + 2][lr] = kk.z; Ks[lc + 3][lr] = kk.w;
        __syncthreads();
#pragma unroll
        for (int k = 0; k < 16; k++) {
            float ra[4], rb[4];
#pragma unroll
            for (int i = 0; i < 4; i++) ra[i] = Qs[k][ty * 4 + i];
#pragma unroll
            for (int j = 0; j < 4; j++) rb[j] = Ks[k][tx * 4 + j];
#pragma unroll
            for (int i = 0; i < 4; i++)
#pragma unroll
                for (int j = 0; j < 4; j++)
                    acc[i][j] = fmaf(ra[i], rb[j], acc[i][j]);
        }
        __syncthreads();
    }
#pragma unroll
    for (int i = 0; i < 4; i++) {
        float* srow = sc + ((size_t)bh * SEQ + qi0 + ty * 4 + i) * SEQ + ki0 + tx * 4;
        *(float4*)srow = make_float4(acc[i][0] * 0.125f, acc[i][1] * 0.125f,
                                     acc[i][2] * 0.125f, acc[i][3] * 0.125f);
    }
}

// ---------------- masked softmax ----------------
__global__ void __launch_bounds__(256) softmax_kernel(float* __restrict__ sc,
                                                      const int* __restrict__ lengths) {
    int gw = (blockIdx.x * blockDim.x + threadIdx.x) >> 5;
    int lane = threadIdx.x & 31;
    if (gw >= BATCH * NHEAD * SEQ) return;
    int b = gw >> 13;
    int len = lengths[b];
    float* row = sc + (size_t)gw * SEQ;
    float v[16];
    float mx = -1e30f;
#pragma unroll
    for (int i = 0; i < 16; i++) {
        int c = lane + i * 32;
        v[i] = (c < len) ? row[c] : -1e30f;
        mx = fmaxf(mx, v[i]);
    }
#pragma unroll
    for (int off = 16; off; off >>= 1) mx = fmaxf(mx, __shfl_xor_sync(0xffffffffu, mx, off));
    float s = 0.f;
#pragma unroll
    for (int i = 0; i < 16; i++) {
        int c = lane + i * 32;
        v[i] = (c < len) ? __expf(v[i] - mx) : 0.f;
        s += v[i];
    }
#pragma unroll
    for (int off = 16; off; off >>= 1) s += __shfl_xor_sync(0xffffffffu, s, off);
    float inv = 1.f / s;
#pragma unroll
    for (int i = 0; i < 16; i++) row[lane + i * 32] = v[i] * inv;
}

// ---------------- AV -> bf16 hi/lo ----------------
__global__ void __launch_bounds__(256) av_kernel(const float* __restrict__ sc,
                                                 const float* __restrict__ kv,
                                                 bf16* __restrict__ oh, bf16* __restrict__ ol) {
    int bh = blockIdx.z;
    int b = bh >> 4, h = bh & 15;
    int qi0 = blockIdx.y << 6;
    __shared__ float Ps[16][68], Vs[16][68];
    int tid = threadIdx.x;
    int tx = tid & 15, ty = tid >> 4;
    float acc[4][4] = {};
    const float* prow = sc + ((size_t)bh * SEQ + qi0) * SEQ;
    const float* vbase = kv + (size_t)b * SEQ * KVW + NHEAD * DHEAD + h * DHEAD;
    int lr = tid >> 2, lc = (tid & 3) << 2;
    int vr = tid >> 4, vc = (tid & 15) << 2;
    for (int k0 = 0; k0 < SEQ; k0 += 16) {
        float4 pv = *(const float4*)(prow + (size_t)lr * SEQ + k0 + lc);
        Ps[lc + 0][lr] = pv.x; Ps[lc + 1][lr] = pv.y; Ps[lc + 2][lr] = pv.z; Ps[lc + 3][lr] = pv.w;
        *(float4*)&Vs[vr][vc] = *(const float4*)(vbase + (size_t)(k0 + vr) * KVW + vc);
        __syncthreads();
#pragma unroll
        for (int k = 0; k < 16; k++) {
            float ra[4], rb[4];
#pragma unroll
            for (int i = 0; i < 4; i++) ra[i] = Ps[k][ty * 4 + i];
#pragma unroll
            for (int j = 0; j < 4; j++) rb[j] = Vs[k][tx * 4 + j];
#pragma unroll
            for (int i = 0; i < 4; i++)
#pragma unroll
                for (int j = 0; j < 4; j++)
                    acc[i][j] = fmaf(ra[i], rb[j], acc[i][j]);
        }
        __syncthreads();
    }
#pragma unroll
    for (int i = 0; i < 4; i++) {
        size_t base = ((size_t)(b * SEQ) + qi0 + ty * 4 + i) * DMODEL + h * DHEAD + tx * 4;
#pragma unroll
        for (int j = 0; j < 4; j++) {
            float v = acc[i][j];
            bf16 hh = __float2bfloat16(v);
            oh[base + j] = hh;
            ol[base + j] = __float2bfloat16(v - __bfloat162float(hh));
        }
    }
}

// ---------------- host ----------------
extern "C" void kernel_launch(void* const* d_in, const int* in_sizes, int n_in,
                              void* d_out, int out_size) {
    const int*   tokens = (const int*)  d_in[0];
    const int*   lengths= (const int*)  d_in[1];
    const float* emb    = (const float*)d_in[2];
    const float* Wq     = (const float*)d_in[3];
    const float* bq     = (const float*)d_in[4];
    const float* Wkv    = (const float*)d_in[5];
    const float* bkv    = (const float*)d_in[6];
    const float* Wo     = (const float*)d_in[7];
    const float* bo     = (const float*)d_in[8];
    const float* lag    = (const float*)d_in[9];
    const float* lab    = (const float*)d_in[10];
    const float* W1     = (const float*)d_in[11];
    const float* b1     = (const float*)d_in[12];
    const float* W2     = (const float*)d_in[13];
    const float* b2     = (const float*)d_in[14];
    const float* lfg    = (const float*)d_in[15];
    const float* lfb    = (const float*)d_in[16];
    const float* lng    = (const float*)d_in[17];
    const float* lnb    = (const float*)d_in[18];

    float *x, *q, *kv, *sc, *pe;
    bf16 *hh, *hl, *oh, *ol, *fh, *fl;
    bf16 *wqh, *wql, *wkvh, *wkvl, *woh, *wol, *w1h, *w1l, *w2h, *w2l;
    cudaGetSymbolAddress((void**)&x, g_x);
    cudaGetSymbolAddress((void**)&q, g_q);
    cudaGetSymbolAddress((void**)&kv, g_kv);
    cudaGetSymbolAddress((void**)&sc, g_sc);
    cudaGetSymbolAddress((void**)&pe, g_pe);
    cudaGetSymbolAddress((void**)&hh, g_hh);
    cudaGetSymbolAddress((void**)&hl, g_hl);
    cudaGetSymbolAddress((void**)&oh, g_oh);
    cudaGetSymbolAddress((void**)&ol, g_ol);
    cudaGetSymbolAddress((void**)&fh, g_fh);
    cudaGetSymbolAddress((void**)&fl, g_fl);
    cudaGetSymbolAddress((void**)&wqh, g_wqT_h);  cudaGetSymbolAddress((void**)&wql, g_wqT_l);
    cudaGetSymbolAddress((void**)&wkvh, g_wkvT_h); cudaGetSymbolAddress((void**)&wkvl, g_wkvT_l);
    cudaGetSymbolAddress((void**)&woh, g_woT_h);  cudaGetSymbolAddress((void**)&wol, g_woT_l);
    cudaGetSymbolAddress((void**)&w1h, g_w1T_h);  cudaGetSymbolAddress((void**)&w1l, g_w1T_l);
    cudaGetSymbolAddress((void**)&w2h, g_w2T_h);  cudaGetSymbolAddress((void**)&w2l, g_w2T_l);

    cudaFuncSetAttribute(tgemm<0>, cudaFuncAttributeMaxDynamicSharedMemorySize, SMEM_T);
    cudaFuncSetAttribute(tgemm<1>, cudaFuncAttributeMaxDynamicSharedMemorySize, SMEM_T);
    cudaFuncSetAttribute(tgemm<2>, cudaFuncAttributeMaxDynamicSharedMemorySize, SMEM_T);

    dim3 tb(32, 8);
    wsplit<<<dim3(DMODEL / 32, DMODEL / 32, NLAYER), tb>>>(Wq,  wqh,  wql,  DMODEL, DMODEL);
    wsplit<<<dim3(KVW / 32,    DMODEL / 32, NLAYER), tb>>>(Wkv, wkvh, wkvl, DMODEL, KVW);
    wsplit<<<dim3(DMODEL / 32, DMODEL / 32, NLAYER), tb>>>(Wo,  woh,  wol,  DMODEL, DMODEL);
    wsplit<<<dim3(DFF / 32,    DMODEL / 32, NLAYER), tb>>>(W1,  w1h,  w1l,  DMODEL, DFF);
    wsplit<<<dim3(DMODEL / 32, DFF / 32,    NLAYER), tb>>>(W2,  w2h,  w2l,  DFF,    DMODEL);

    pe_kernel<<<(SEQ * DMODEL) / 256, 256>>>(pe);
    embed_kernel<<<(NTOK * DMODEL) / 256, 256>>>(tokens, emb, pe, x);

    for (int l = 0; l < NLAYER; l++) {
        size_t oQ = (size_t)l * DMODEL * DMODEL;
        size_t oKV = (size_t)l * DMODEL * KVW;
        size_t o1 = (size_t)l * DMODEL * DFF;

        // attention sublayer
        ln_kernel<1><<<NTOK, 256>>>(x, lag + l * DMODEL, lab + l * DMODEL, nullptr, hh, hl);
        tgemm<0><<<dim3(DMODEL / 256, NTOK / 128), 256, SMEM_T>>>(
            hh, hl, wqh + oQ, wql + oQ, bq + l * DMODEL, q, nullptr, nullptr, DMODEL, DMODEL);
        tgemm<0><<<dim3(KVW / 256, NTOK / 128), 256, SMEM_T>>>(
            hh, hl, wkvh + oKV, wkvl + oKV, bkv + l * KVW, kv, nullptr, nullptr, KVW, DMODEL);
        scores_kernel<<<dim3(SEQ / 64, SEQ / 64, BATCH * NHEAD), 256>>>(q, kv, sc);
        softmax_kernel<<<(BATCH * NHEAD * SEQ * 32) / 256, 256>>>(sc, lengths);
        av_kernel<<<dim3(1, SEQ / 64, BATCH * NHEAD), 256>>>(sc, kv, oh, ol);
        tgemm<1><<<dim3(DMODEL / 256, NTOK / 128), 256, SMEM_T>>>(
            oh, ol, woh + oQ, wol + oQ, bo + l * DMODEL, x, nullptr, nullptr, DMODEL, DMODEL);

        // FFN sublayer
        ln_kernel<1><<<NTOK, 256>>>(x, lfg + l * DMODEL, lfb + l * DMODEL, nullptr, hh, hl);
        tgemm<2><<<dim3(DFF / 256, NTOK / 128), 256, SMEM_T>>>(
            hh, hl, w1h + o1, w1l + o1, b1 + l * DFF, nullptr, fh, fl, DFF, DMODEL);
        tgemm<1><<<dim3(DMODEL / 256, NTOK / 128), 256, SMEM_T>>>(
            fh, fl, w2h + o1, w2l + o1, b2 + l * DMODEL, x, nullptr, nullptr, DMODEL, DFF);
    }

    ln_kernel<0><<<NTOK, 256>>>(x, lng, lnb, (float*)d_out, nullptr, nullptr);
}